// round 3
// baseline (speedup 1.0000x reference)
#include <cuda_runtime.h>
#include <cuda_bf16.h>

// SparseVoxelEncoder: trilinear interpolation of 8 corner embeddings per point.
// P = 1048576 points, H = 524288 voxels, NEMB = 600000 embeddings, D = 32.
//
// Indices (sampled_idx, point_feats) are int32: JAX without x64 downgrades
// jnp.int64 to int32. (R1 read them as int64 -> garbage indices -> fault.)
//
// Strategy: 8 lanes per point (one per corner). Lane c computes its corner's
// trilinear weight + embedding index, shuffles broadcast (e, w) within the
// 8-lane group, then every lane accumulates its float4 slice of the D=32
// output across all 8 corners. Each values-row gather is one full 128B line
// (zero waste); values table (76.8 MB) is L2-resident, so the kernel is
// L2-throughput-bound.

#define P_TOTAL 1048576
#define NTHREADS 256

__global__ __launch_bounds__(NTHREADS)
void sve_trilerp_kernel(const float* __restrict__ sampled_xyz,   // [P,3]
                        const float* __restrict__ point_xyz,     // [H,3]
                        const float* __restrict__ values,        // [NEMB,32]
                        const int*  __restrict__ sampled_idx,    // [P] int32
                        const int*  __restrict__ point_feats,    // [H,8] int32
                        float* __restrict__ out)                 // [P,32]
{
    const int tid   = blockIdx.x * NTHREADS + threadIdx.x;
    const int point = tid >> 3;        // 8 lanes per point
    const int c     = tid & 7;         // this lane's corner id (0..7)
    const int gbase = threadIdx.x & 24;// group base lane within warp

    // ---- per-point scalars (broadcast across the 8-lane group via L1) ----
    const int h = __ldg(&sampled_idx[point]);

    const float sx = __ldg(&sampled_xyz[3 * point + 0]);
    const float sy = __ldg(&sampled_xyz[3 * point + 1]);
    const float sz = __ldg(&sampled_xyz[3 * point + 2]);
    const float px = __ldg(&point_xyz[3 * h + 0]);
    const float py = __ldg(&point_xyz[3 * h + 1]);
    const float pz = __ldg(&point_xyz[3 * h + 2]);

    // normalized position inside voxel, in [0,1]^3 (1/VOXEL_SIZE = 4)
    const float p0 = (sx - px) * 4.0f + 0.5f;
    const float p1 = (sy - py) * 4.0f + 0.5f;
    const float p2 = (sz - pz) * 4.0f + 0.5f;

    // corner q = (c>>2, (c>>1)&1, c&1); weight per dim = q ? p : (1-p)
    const float wx = (c & 4) ? p0 : 1.0f - p0;
    const float wy = (c & 2) ? p1 : 1.0f - p1;
    const float wz = (c & 1) ? p2 : 1.0f - p2;
    const float w  = wx * wy * wz;

    // this lane's corner embedding id
    const int e = __ldg(&point_feats[(size_t)h * 8 + c]);

    // ---- broadcast (e, w) of all 8 corners within the group ----
    int   ek[8];
    float wk[8];
#pragma unroll
    for (int k = 0; k < 8; ++k) {
        ek[k] = __shfl_sync(0xffffffffu, e, gbase + k);
        wk[k] = __shfl_sync(0xffffffffu, w, gbase + k);
    }

    // ---- gather: lane c reads float4 slice [4c..4c+3] of each corner row ----
    const float4* __restrict__ vrows = (const float4*)values; // row = 8 float4
    float4 f[8];
#pragma unroll
    for (int k = 0; k < 8; ++k)
        f[k] = __ldg(&vrows[(size_t)ek[k] * 8 + c]);

    float4 acc = make_float4(0.f, 0.f, 0.f, 0.f);
#pragma unroll
    for (int k = 0; k < 8; ++k) {
        acc.x = fmaf(wk[k], f[k].x, acc.x);
        acc.y = fmaf(wk[k], f[k].y, acc.y);
        acc.z = fmaf(wk[k], f[k].z, acc.z);
        acc.w = fmaf(wk[k], f[k].w, acc.w);
    }

    ((float4*)out)[(size_t)point * 8 + c] = acc;
}

extern "C" void kernel_launch(void* const* d_in, const int* in_sizes, int n_in,
                              void* d_out, int out_size)
{
    const float* sampled_xyz = (const float*)d_in[0];
    const float* point_xyz   = (const float*)d_in[1];
    const float* values      = (const float*)d_in[2];
    const int*   sampled_idx = (const int*)d_in[3];
    const int*   point_feats = (const int*)d_in[4];
    float*       out         = (float*)d_out;

    const int threads = NTHREADS;
    const int blocks  = (P_TOTAL * 8) / threads; // 32768
    sve_trilerp_kernel<<<blocks, threads>>>(sampled_xyz, point_xyz, values,
                                            sampled_idx, point_feats, out);
}

// round 4
// speedup vs baseline: 1.0373x; 1.0373x over previous
#include <cuda_runtime.h>
#include <cuda_bf16.h>

// SparseVoxelEncoder: trilinear interpolation of 8 corner embeddings per point.
// P = 1048576 points, H = 524288 voxels, NEMB = 600000 embeddings, D = 32.
//
// R2 (104.9us) profile: DRAM 64.9% (5.1TB/s, ~540MB) vs ~245MB compulsory ->
// values rows (77MB table, ~13 refs/row) are thrashed out of L2 by the 128MB
// output write stream. R3: streaming hints — __stcs on output, __ldcs on the
// once-read input streams — so L2 capacity stays dedicated to the values table.
//
// Layout: 8 lanes per point (one per corner). Lane c computes its corner's
// weight + embedding id, shuffle-broadcasts (e,w) across the 8-lane group,
// then every lane gathers its float4 slice of each of the 8 corner rows
// (one full 128B line per row-ref, zero waste; 8 loads in flight).

#define P_TOTAL 1048576
#define NTHREADS 256

__global__ __launch_bounds__(NTHREADS)
void sve_trilerp_kernel(const float* __restrict__ sampled_xyz,   // [P,3]
                        const float* __restrict__ point_xyz,     // [H,3]
                        const float* __restrict__ values,        // [NEMB,32]
                        const int*  __restrict__ sampled_idx,    // [P] int32
                        const int*  __restrict__ point_feats,    // [H,8] int32
                        float* __restrict__ out)                 // [P,32]
{
    const int tid   = blockIdx.x * NTHREADS + threadIdx.x;
    const int point = tid >> 3;        // 8 lanes per point
    const int c     = tid & 7;         // this lane's corner id (0..7)
    const int gbase = threadIdx.x & 24;// group base lane within warp

    // ---- per-point scalars ----
    // sampled_idx / sampled_xyz are read exactly once -> streaming loads
    const int h = __ldcs(&sampled_idx[point]);

    const float sx = __ldcs(&sampled_xyz[3 * point + 0]);
    const float sy = __ldcs(&sampled_xyz[3 * point + 1]);
    const float sz = __ldcs(&sampled_xyz[3 * point + 2]);
    // point_xyz / point_feats have ~2x reuse (2 points/voxel) -> cached
    const float px = __ldg(&point_xyz[3 * h + 0]);
    const float py = __ldg(&point_xyz[3 * h + 1]);
    const float pz = __ldg(&point_xyz[3 * h + 2]);

    // normalized position inside voxel, in [0,1]^3 (1/VOXEL_SIZE = 4)
    const float p0 = (sx - px) * 4.0f + 0.5f;
    const float p1 = (sy - py) * 4.0f + 0.5f;
    const float p2 = (sz - pz) * 4.0f + 0.5f;

    // corner q = (c>>2, (c>>1)&1, c&1); weight per dim = q ? p : (1-p)
    const float wx = (c & 4) ? p0 : 1.0f - p0;
    const float wy = (c & 2) ? p1 : 1.0f - p1;
    const float wz = (c & 1) ? p2 : 1.0f - p2;
    const float w  = wx * wy * wz;

    // this lane's corner embedding id
    const int e = __ldg(&point_feats[(size_t)h * 8 + c]);

    // ---- broadcast (e, w) of all 8 corners within the group ----
    int   ek[8];
    float wk[8];
#pragma unroll
    for (int k = 0; k < 8; ++k) {
        ek[k] = __shfl_sync(0xffffffffu, e, gbase + k);
        wk[k] = __shfl_sync(0xffffffffu, w, gbase + k);
    }

    // ---- gather: lane c reads float4 slice [4c..4c+3] of each corner row ----
    // values table is the L2-resident hot set: default cached loads.
    const float4* __restrict__ vrows = (const float4*)values; // row = 8 float4
    float4 f[8];
#pragma unroll
    for (int k = 0; k < 8; ++k)
        f[k] = __ldg(&vrows[(size_t)ek[k] * 8 + c]);

    float4 acc = make_float4(0.f, 0.f, 0.f, 0.f);
#pragma unroll
    for (int k = 0; k < 8; ++k) {
        acc.x = fmaf(wk[k], f[k].x, acc.x);
        acc.y = fmaf(wk[k], f[k].y, acc.y);
        acc.z = fmaf(wk[k], f[k].z, acc.z);
        acc.w = fmaf(wk[k], f[k].w, acc.w);
    }

    // output is write-once -> streaming (evict-first) store, keep L2 for values
    __stcs(&((float4*)out)[(size_t)point * 8 + c], acc);
}

extern "C" void kernel_launch(void* const* d_in, const int* in_sizes, int n_in,
                              void* d_out, int out_size)
{
    const float* sampled_xyz = (const float*)d_in[0];
    const float* point_xyz   = (const float*)d_in[1];
    const float* values      = (const float*)d_in[2];
    const int*   sampled_idx = (const int*)d_in[3];
    const int*   point_feats = (const int*)d_in[4];
    float*       out         = (float*)d_out;

    const int threads = NTHREADS;
    const int blocks  = (P_TOTAL * 8) / threads; // 32768
    sve_trilerp_kernel<<<blocks, threads>>>(sampled_xyz, point_xyz, values,
                                            sampled_idx, point_feats, out);
}